// round 6
// baseline (speedup 1.0000x reference)
#include <cuda_runtime.h>
#include <math.h>

// DGPLoss fused single-kernel, whole-band blocks + 2-deep pipelined centers:
//   seg_feat: [4, 64, 512, 512] fp32   (d_in[0])
//   dep_true: [4, 1, 512, 512]  fp32   (d_in[1])
//   out[0]  : scalar fp32
//
// Block = one 5-row patch band x batch (408 blocks, 640 thr). Thread = 4 px
// (LDG.128). Row-2 warps extract patch centers from their own pixel loads
// into double-buffered smem. Software pipeline: channel g+2's LDG is issued
// BEFORE the barrier that closes channel g, so each warp keeps 2 loads in
// flight and the dependent use (center store of g+1) waits on a load issued
// a full iteration earlier. Ticket-elected last block reduces 408 partials.

#define EPSF 1e-8f
#define EPS2 1e-16f
#define CS   262144              // 512*512
#define NBANDS 102
#define NBAT 4
#define NPART (NBANDS * NBAT)    // 408

__device__ float2       g_part[NPART];
__device__ unsigned int g_ticket;   // zero-init; reset by last block each run

__device__ __forceinline__ float selq(float4 v, int off) {
    const float lo = (off & 1) ? v.y : v.x;
    const float hi = (off & 1) ? v.w : v.z;
    return (off & 2) ? hi : lo;
}

__device__ __forceinline__ float4 ldcs4(const float4* p) {
    return __ldcs(p);   // streaming: no reuse of pixel data
}

__global__ __launch_bounds__(640, 3)
void dgp_fused(const float* __restrict__ seg, const float* __restrict__ dep,
               float* __restrict__ out)
{
    __shared__ float  s_c[2][104];   // double-buffered per-channel centers
    __shared__ float  s_dc[104];     // depth centers
    __shared__ float2 s_red[20];
    __shared__ bool   isLast;

    const int tid = threadIdx.x;
    const int r   = tid >> 7;        // row within band: 0..4
    const int wl  = tid & 127;
    const int w0  = wl << 2;         // 0..508
    const int j   = blockIdx.x;      // band 0..101
    const int b   = blockIdx.y;      // batch 0..3
    const int h   = j * 5 + r;

    const int  pA  = w0 / 5;
    const int  pB  = (w0 + 3) / 5;   // may be 102 (pad slot, masked)
    const bool sB1 = ((w0 + 1) / 5) != pA;
    const bool sB2 = ((w0 + 2) / 5) != pA;
    const bool sB3 = (pB != pA);

    // center-extraction constants: the one column in [w0,w0+3] with col%5==2
    const int  rem = w0 - pA * 5;
    const int  off = (7 - rem) % 5;          // 0..4; 4 => no center in quad
    const bool has = (r == 2) && (off < 4);
    const int  cp  = (w0 + off) / 5;         // patch index of that center

    // zero pad slots once (reads of pads are masked; keep them finite).
    // only center stores (cp < 102) touch s_c afterwards, so pads persist.
    if (tid < 2)       s_c[0][102 + tid] = 0.f;
    else if (tid < 4)  s_c[1][100 + tid] = 0.f;
    else if (tid < 6)  s_dc[98 + tid]    = 0.f;

    const float4* __restrict__ pix =
        (const float4*)(seg + (size_t)b * 64 * CS + (size_t)h * 512 + w0);

    float a0 = 0.f, a1 = 0.f, a2 = 0.f, a3 = 0.f;

    // prologue: ch0 + ch1 in flight; publish ch0 centers
    float4 pc = ldcs4(pix);
    float4 pn = ldcs4(pix + (CS / 4));
    if (has) s_c[0][cp] = selq(pc, off);
    __syncthreads();

    #pragma unroll 8
    for (int g = 0; g < 64; ++g) {
        // publish centers of ch g+1 (pn was loaded >= 1 iteration ago)
        if (g < 63) {
            if (has) s_c[(g + 1) & 1][cp] = selq(pn, off);
        }
        // issue LDG for ch g+2 before the barrier
        float4 pnn = pn;
        if (g < 62) pnn = ldcs4(pix + (g + 2) * (CS / 4));

        // compute ch g against its (already visible) centers
        const float qA = s_c[g & 1][pA];
        const float qB = s_c[g & 1][pB];
        const float q1 = sB1 ? qB : qA;
        const float q2 = sB2 ? qB : qA;
        const float q3 = sB3 ? qB : qA;
        float d;
        d = qA - pc.x; a0 = fmaf(d, d, a0);
        d = q1 - pc.y; a1 = fmaf(d, d, a1);
        d = q2 - pc.z; a2 = fmaf(d, d, a2);
        d = q3 - pc.w; a3 = fmaf(d, d, a3);

        __syncthreads();   // publishes ch g+1 centers; ends reads of buf g&1
        pc = pn; pn = pnn;
    }

    // ---- depth branch ----
    const float4 dq = __ldcs((const float4*)(dep + (size_t)b * CS + (size_t)h * 512 + w0));
    if (has) s_dc[cp] = selq(dq, off);
    __syncthreads();

    const float dcA = s_dc[pA];
    const float dcB = s_dc[pB];
    const int   wcA = pA * 5 + 2;
    const int   wcB = pB * 5 + 2;

    const float dcv[4] = { dcA, sB1 ? dcB : dcA, sB2 ? dcB : dcA, sB3 ? dcB : dcA };
    const int   wcv[4] = { wcA, sB1 ? wcB : wcA, sB2 ? wcB : wcA, sB3 ? wcB : wcA };
    const float av [4] = { a0, a1, a2, a3 };
    const float dpv[4] = { dq.x, dq.y, dq.z, dq.w };

    float sum = 0.f, cnt = 0.f;
    #pragma unroll
    for (int k = 0; k < 4; ++k) {
        const float dd = fabsf(dcv[k] - dpv[k]);
        const bool ic  = (r == 2) && (w0 + k == wcv[k]);
        const bool m   = (dd > EPSF) && (av[k] > EPS2) && (dpv[k] > EPSF) &&
                         !ic && (w0 + k < 510);
        if (m) {
            sum += __expf(-fmaf(dd, 0.1f, av[k]));
            cnt += 1.f;
        }
    }

    // ---- block reduce (20 warps) ----
    #pragma unroll
    for (int o = 16; o > 0; o >>= 1) {
        sum += __shfl_down_sync(0xFFFFFFFFu, sum, o);
        cnt += __shfl_down_sync(0xFFFFFFFFu, cnt, o);
    }
    const int lane = tid & 31;
    const int wid  = tid >> 5;
    if (lane == 0) s_red[wid] = make_float2(sum, cnt);
    __syncthreads();

    if (wid == 0) {
        float s = (lane < 20) ? s_red[lane].x : 0.f;
        float c = (lane < 20) ? s_red[lane].y : 0.f;
        #pragma unroll
        for (int o = 16; o > 0; o >>= 1) {
            s += __shfl_down_sync(0xFFFFFFFFu, s, o);
            c += __shfl_down_sync(0xFFFFFFFFu, c, o);
        }
        if (lane == 0) {
            g_part[j + NBANDS * b] = make_float2(s, c);
            __threadfence();
            const unsigned t = atomicAdd(&g_ticket, 1u);
            isLast = (t == NPART - 1);
        }
    }
    __syncthreads();

    // ---- final deterministic reduction by the last block ----
    if (isLast) {
        __threadfence();
        float s = 0.f, c = 0.f;
        if (tid < NPART) {               // 408 < 640: one partial per thread
            const float2 v = g_part[tid];
            s = v.x; c = v.y;
        }
        #pragma unroll
        for (int o = 16; o > 0; o >>= 1) {
            s += __shfl_down_sync(0xFFFFFFFFu, s, o);
            c += __shfl_down_sync(0xFFFFFFFFu, c, o);
        }
        __syncthreads();                 // s_red reuse
        if (lane == 0) s_red[wid] = make_float2(s, c);
        __syncthreads();
        if (wid == 0) {
            float ts = (lane < 20) ? s_red[lane].x : 0.f;
            float tc = (lane < 20) ? s_red[lane].y : 0.f;
            #pragma unroll
            for (int o = 16; o > 0; o >>= 1) {
                ts += __shfl_down_sync(0xFFFFFFFFu, ts, o);
                tc += __shfl_down_sync(0xFFFFFFFFu, tc, o);
            }
            if (lane == 0) {
                out[0] = ts / fmaxf(tc, 1.0f);
                g_ticket = 0u;           // reset for next graph replay
            }
        }
    }
}

extern "C" void kernel_launch(void* const* d_in, const int* in_sizes, int n_in,
                              void* d_out, int out_size) {
    const float* seg = (const float*)d_in[0];   // [4,64,512,512]
    const float* dep = (const float*)d_in[1];   // [4,1,512,512]
    float* out = (float*)d_out;

    dim3 grid(NBANDS, NBAT);
    dgp_fused<<<grid, 640>>>(seg, dep, out);
}

// round 7
// speedup vs baseline: 1.1678x; 1.1678x over previous
#include <cuda_runtime.h>
#include <math.h>

// DGPLoss fused single-kernel, whole-band blocks, depth-2 center pipeline:
//   seg_feat: [4, 64, 512, 512] fp32   (d_in[0])
//   dep_true: [4, 1, 512, 512]  fp32   (d_in[1])
//   out[0]  : scalar fp32
//
// Block = one 5-row patch band x batch (408 blocks, 640 thr, 3 blocks/SM).
// Thread = 4 px (LDG.128). Row-2 warps extract patch centers from their own
// pixel loads into double-buffered smem. Pipeline: channel g+2's load is
// issued at iteration g (clamped index, no conditional copies), so the
// center store of channel g+1 — which gates the per-iteration barrier —
// consumes a load issued one full iteration earlier. Ticket-elected last
// block does the deterministic final reduction over 408 partials.

#define EPSF 1e-8f
#define EPS2 1e-16f
#define CS   262144              // 512*512
#define CS4  (CS / 4)
#define NBANDS 102
#define NBAT 4
#define NPART (NBANDS * NBAT)    // 408

__device__ float2       g_part[NPART];
__device__ unsigned int g_ticket;   // zero-init; reset by last block each run

__device__ __forceinline__ float selq(float4 v, int off) {
    const float lo = (off & 1) ? v.y : v.x;
    const float hi = (off & 1) ? v.w : v.z;
    return (off & 2) ? hi : lo;
}

__global__ __launch_bounds__(640, 3)
void dgp_fused(const float* __restrict__ seg, const float* __restrict__ dep,
               float* __restrict__ out)
{
    __shared__ float  s_c[2][104];   // double-buffered per-channel centers
    __shared__ float  s_dc[104];     // depth centers
    __shared__ float2 s_red[20];
    __shared__ bool   isLast;

    const int tid = threadIdx.x;
    const int r   = tid >> 7;        // row within band: 0..4
    const int wl  = tid & 127;
    const int w0  = wl << 2;         // 0..508
    const int j   = blockIdx.x;      // band 0..101
    const int b   = blockIdx.y;      // batch 0..3
    const int h   = j * 5 + r;

    const int  pA  = w0 / 5;
    const int  pB  = (w0 + 3) / 5;   // may be 102 (pad slot, masked)
    const bool sB1 = ((w0 + 1) / 5) != pA;
    const bool sB2 = ((w0 + 2) / 5) != pA;
    const bool sB3 = (pB != pA);

    // center-extraction constants: the one column in [w0,w0+3] with col%5==2
    const int  rem = w0 - pA * 5;
    const int  off = (7 - rem) % 5;          // 0..4; 4 => no center in quad
    const bool has = (r == 2) && (off < 4);
    const int  cp  = (w0 + off) / 5;         // patch index of that center

    // zero pad slots once (reads of pads are masked; keep them finite).
    if (tid < 2)       s_c[0][102 + tid] = 0.f;
    else if (tid < 4)  s_c[1][100 + tid] = 0.f;
    else if (tid < 6)  s_dc[98 + tid]    = 0.f;

    const float4* __restrict__ pix =
        (const float4*)(seg + (size_t)b * 64 * CS + (size_t)h * 512 + w0);

    float a0 = 0.f, a1 = 0.f, a2 = 0.f, a3 = 0.f;

    // prologue: ch0, ch1 in flight; publish ch0 centers
    float4 pc = pix[0];
    float4 pn = pix[CS4];
    if (has) s_c[0][cp] = selq(pc, off);
    __syncthreads();

    #pragma unroll 4
    for (int g = 0; g < 64; ++g) {
        // issue ch g+2's load immediately (clamped: dup ch63 loads are L1 hits)
        const int gn = (g + 2 < 64) ? g + 2 : 63;
        const float4 pnn = pix[gn * CS4];

        // publish centers of ch g+1 (pn was issued one full iteration ago)
        if ((g < 63) && has) s_c[(g + 1) & 1][cp] = selq(pn, off);

        // compute ch g against its (already visible) centers
        const float qA = s_c[g & 1][pA];
        const float qB = s_c[g & 1][pB];
        const float q1 = sB1 ? qB : qA;
        const float q2 = sB2 ? qB : qA;
        const float q3 = sB3 ? qB : qA;
        float d;
        d = qA - pc.x; a0 = fmaf(d, d, a0);
        d = q1 - pc.y; a1 = fmaf(d, d, a1);
        d = q2 - pc.z; a2 = fmaf(d, d, a2);
        d = q3 - pc.w; a3 = fmaf(d, d, a3);

        __syncthreads();   // publishes ch g+1 centers; closes reads of buf g&1
        pc = pn; pn = pnn;
    }

    // ---- depth branch ----
    const float4 dq = *(const float4*)(dep + (size_t)b * CS + (size_t)h * 512 + w0);
    if (has) s_dc[cp] = selq(dq, off);
    __syncthreads();

    const float dcA = s_dc[pA];
    const float dcB = s_dc[pB];
    const int   wcA = pA * 5 + 2;
    const int   wcB = pB * 5 + 2;

    const float dcv[4] = { dcA, sB1 ? dcB : dcA, sB2 ? dcB : dcA, sB3 ? dcB : dcA };
    const int   wcv[4] = { wcA, sB1 ? wcB : wcA, sB2 ? wcB : wcA, sB3 ? wcB : wcA };
    const float av [4] = { a0, a1, a2, a3 };
    const float dpv[4] = { dq.x, dq.y, dq.z, dq.w };

    float sum = 0.f, cnt = 0.f;
    #pragma unroll
    for (int k = 0; k < 4; ++k) {
        const float dd = fabsf(dcv[k] - dpv[k]);
        const bool ic  = (r == 2) && (w0 + k == wcv[k]);
        const bool m   = (dd > EPSF) && (av[k] > EPS2) && (dpv[k] > EPSF) &&
                         !ic && (w0 + k < 510);
        if (m) {
            sum += __expf(-fmaf(dd, 0.1f, av[k]));
            cnt += 1.f;
        }
    }

    // ---- block reduce (20 warps) ----
    #pragma unroll
    for (int o = 16; o > 0; o >>= 1) {
        sum += __shfl_down_sync(0xFFFFFFFFu, sum, o);
        cnt += __shfl_down_sync(0xFFFFFFFFu, cnt, o);
    }
    const int lane = tid & 31;
    const int wid  = tid >> 5;
    if (lane == 0) s_red[wid] = make_float2(sum, cnt);
    __syncthreads();

    if (wid == 0) {
        float s = (lane < 20) ? s_red[lane].x : 0.f;
        float c = (lane < 20) ? s_red[lane].y : 0.f;
        #pragma unroll
        for (int o = 16; o > 0; o >>= 1) {
            s += __shfl_down_sync(0xFFFFFFFFu, s, o);
            c += __shfl_down_sync(0xFFFFFFFFu, c, o);
        }
        if (lane == 0) {
            g_part[j + NBANDS * b] = make_float2(s, c);
            __threadfence();
            const unsigned t = atomicAdd(&g_ticket, 1u);
            isLast = (t == NPART - 1);
        }
    }
    __syncthreads();

    // ---- final deterministic reduction by the last block ----
    if (isLast) {
        __threadfence();
        float s = 0.f, c = 0.f;
        if (tid < NPART) {               // 408 < 640: one partial per thread
            const float2 v = g_part[tid];
            s = v.x; c = v.y;
        }
        #pragma unroll
        for (int o = 16; o > 0; o >>= 1) {
            s += __shfl_down_sync(0xFFFFFFFFu, s, o);
            c += __shfl_down_sync(0xFFFFFFFFu, c, o);
        }
        __syncthreads();                 // s_red reuse
        if (lane == 0) s_red[wid] = make_float2(s, c);
        __syncthreads();
        if (wid == 0) {
            float ts = (lane < 20) ? s_red[lane].x : 0.f;
            float tc = (lane < 20) ? s_red[lane].y : 0.f;
            #pragma unroll
            for (int o = 16; o > 0; o >>= 1) {
                ts += __shfl_down_sync(0xFFFFFFFFu, ts, o);
                tc += __shfl_down_sync(0xFFFFFFFFu, tc, o);
            }
            if (lane == 0) {
                out[0] = ts / fmaxf(tc, 1.0f);
                g_ticket = 0u;           // reset for next graph replay
            }
        }
    }
}

extern "C" void kernel_launch(void* const* d_in, const int* in_sizes, int n_in,
                              void* d_out, int out_size) {
    const float* seg = (const float*)d_in[0];   // [4,64,512,512]
    const float* dep = (const float*)d_in[1];   // [4,1,512,512]
    float* out = (float*)d_out;

    dim3 grid(NBANDS, NBAT);
    dgp_fused<<<grid, 640>>>(seg, dep, out);
}